// round 7
// baseline (speedup 1.0000x reference)
#include <cuda_runtime.h>
#include <cuda_bf16.h>

// Problem shape (fixed by the reference)
#define NWALK 4096
#define NIN   24      // NPART*NDIM
#define HID   256
#define TPW   8       // threads cooperating on one walker
#define BLOCK 128
#define STR   28      // padded smem row stride for W1^T (28*4B: lanes sub=0..7 hit distinct banks, 16B aligned)

__global__ __launch_bounds__(BLOCK)
void kin_kernel(const float* __restrict__ x,
                const float* __restrict__ W1,
                const float* __restrict__ b1,
                const float* __restrict__ W2,
                float* __restrict__ out)
{
    __shared__ float sW1t[HID * STR];   // [j][i], padded
    __shared__ float sb1[HID];
    __shared__ float sW2[HID];
    __shared__ float sS[HID];           // S_j = sum_i W1[i][j]^2

    const int tid = threadIdx.x;

    // Load + transpose W1 into shared: global reads coalesced over j.
    for (int k = tid; k < NIN * HID; k += BLOCK) {
        int i = k / HID;
        int j = k - i * HID;
        sW1t[j * STR + i] = W1[k];
    }
    for (int k = tid; k < HID; k += BLOCK) {
        sb1[k] = b1[k];
        sW2[k] = W2[k];
    }
    __syncthreads();

    // Column sums of squares (walker-independent)
    for (int j = tid; j < HID; j += BLOCK) {
        float s = 0.f;
        #pragma unroll
        for (int i = 0; i < NIN; i++) {
            float w = sW1t[j * STR + i];
            s = fmaf(w, w, s);
        }
        sS[j] = s;
    }
    __syncthreads();

    const int gt     = blockIdx.x * BLOCK + tid;
    const int walker = gt >> 3;        // / TPW
    const int sub    = gt & (TPW - 1);

    // Load this walker's z (24 floats, 16B-aligned: walker*96 bytes)
    const float* z = x + walker * NIN;
    float zr[NIN];
    #pragma unroll
    for (int i = 0; i < NIN; i += 4) {
        float4 v = *reinterpret_cast<const float4*>(z + i);
        zr[i] = v.x; zr[i + 1] = v.y; zr[i + 2] = v.z; zr[i + 3] = v.w;
    }

    float g[NIN];
    #pragma unroll
    for (int i = 0; i < NIN; i++) g[i] = 0.f;
    float lap = 0.f;

    // Each lane handles j = jj*8 + sub  (lane-interleaved: conflict-free LDS.128)
    for (int jj = 0; jj < HID / TPW; jj++) {
        const int j = jj * TPW + sub;
        const float* wc = &sW1t[j * STR];

        float w[NIN];
        #pragma unroll
        for (int i = 0; i < NIN; i += 4) {
            float4 v = *reinterpret_cast<const float4*>(wc + i);
            w[i] = v.x; w[i + 1] = v.y; w[i + 2] = v.z; w[i + 3] = v.w;
        }

        // a_j = b1_j + z . W1[:,j]   (4 partial accumulators for ILP)
        float acc0 = sb1[j], acc1 = 0.f, acc2 = 0.f, acc3 = 0.f;
        #pragma unroll
        for (int i = 0; i < NIN; i += 4) {
            acc0 = fmaf(zr[i],     w[i],     acc0);
            acc1 = fmaf(zr[i + 1], w[i + 1], acc1);
            acc2 = fmaf(zr[i + 2], w[i + 2], acc2);
            acc3 = fmaf(zr[i + 3], w[i + 3], acc3);
        }
        const float a = (acc0 + acc1) + (acc2 + acc3);

        // tanh(a) = 1 - t, t = 2/(e^{2a}+1); 1-h^2 = t(2-t) (cancellation-free)
        const float e  = __expf(2.f * a);
        const float t  = __fdividef(2.f, e + 1.f);
        const float h  = 1.f - t;
        const float om = t * (2.f - t);         // 1 - h^2
        const float u  = om * sW2[j];           // tanh'(a) * W2_j

        // laplacian contribution: S_j * (-2 h (1-h^2)) * W2_j
        lap = fmaf(-2.f * h * sS[j], u, lap);

        // gradient accumulation: g_i += W1[i][j] * u  (reuses w[] from registers)
        #pragma unroll
        for (int i = 0; i < NIN; i++) g[i] = fmaf(w[i], u, g[i]);
    }

    // Butterfly reduction across the 8 lanes of this walker (lanes l: l>>3 groups)
    #pragma unroll
    for (int i = 0; i < NIN; i++) {
        g[i] += __shfl_xor_sync(0xffffffffu, g[i], 1);
        g[i] += __shfl_xor_sync(0xffffffffu, g[i], 2);
        g[i] += __shfl_xor_sync(0xffffffffu, g[i], 4);
    }
    lap += __shfl_xor_sync(0xffffffffu, lap, 1);
    lap += __shfl_xor_sync(0xffffffffu, lap, 2);
    lap += __shfl_xor_sync(0xffffffffu, lap, 4);

    if (sub == 0) {
        float gsq = 0.f;
        #pragma unroll
        for (int i = 0; i < NIN; i++) gsq = fmaf(g[i], g[i], gsq);
        out[walker] = -0.5f * (lap + gsq);
    }
}

extern "C" void kernel_launch(void* const* d_in, const int* in_sizes, int n_in,
                              void* d_out, int out_size)
{
    // metadata order: x [4096*8*3], W1 [24*256], b1 [256], W2 [256], b2 [1]
    const float* x  = (const float*)d_in[0];
    const float* W1 = (const float*)d_in[1];
    const float* b1 = (const float*)d_in[2];
    const float* W2 = (const float*)d_in[3];
    // b2 contributes nothing to derivatives
    float* out = (float*)d_out;

    const int grid = (NWALK * TPW) / BLOCK;   // 256 blocks
    kin_kernel<<<grid, BLOCK>>>(x, W1, b1, W2, out);
}